// round 10
// baseline (speedup 1.0000x reference)
#include <cuda_runtime.h>

#define TPB   256
#define WARPS (TPB / 32)
#define EPW   32                 // edges per warp (ILP=1)
#define EPB   (WARPS * EPW)      // 256 edges per block

// Single packed constant image:
//   [0..39]    W1   [4][10] row-major
//   [40..49]   b1
//   [50..249]  W2p  [10][20]  (col 19 of each row = 0)
//   [250..269] b2p  (slot 19 = 0)
// All (2k,2k+1) pair offsets are 8B-aligned for 64-bit constant loads.
__constant__ __align__(16) float cpar[270];
__device__   __align__(16) float g_stage[270];   // built by prep_kernel

// 1 if `batch` is int64 (odd int32 words are zero high-halves), else 0.
__device__ int g_batch_is64;

typedef unsigned long long u64;

__device__ __forceinline__ u64 pack2(float lo, float hi) {
    u64 r; asm("mov.b64 %0, {%1, %2};" : "=l"(r) : "f"(lo), "f"(hi)); return r;
}
__device__ __forceinline__ void unpack2(u64 v, float& lo, float& hi) {
    asm("mov.b64 {%0, %1}, %2;" : "=f"(lo), "=f"(hi) : "l"(v));
}
// Blackwell packed dual-fp32 FMA (2 FLOPs/instr; ptxas never auto-fuses this)
__device__ __forceinline__ u64 ffma2(u64 a, u64 b, u64 c) {
    u64 d; asm("fma.rn.f32x2 %0, %1, %2, %3;" : "=l"(d) : "l"(a), "l"(b), "l"(c));
    return d;
}
__device__ __forceinline__ u64 cpair(const float* p) {   // 8B-aligned const pair
    return *reinterpret_cast<const u64*>(p);
}

// One launch: batch-width detector + padded constant-image staging.
__global__ void prep_kernel(const float* __restrict__ W1,
                            const float* __restrict__ b1,
                            const float* __restrict__ W2,
                            const float* __restrict__ b2,
                            const int* __restrict__ b32)
{
    const int t = threadIdx.x;
    if (t == 0) {
        int z = 0;
#pragma unroll
        for (int i = 1; i < 64; i += 2) z |= b32[i];
        g_batch_is64 = (z == 0) ? 1 : 0;
    }
    if (t < 40) g_stage[t] = W1[t];
    if (t < 10) g_stage[40 + t] = b1[t];
    for (int i = t; i < 200; i += blockDim.x) {          // padded W2
        int j = i / 20, c = i % 20;
        g_stage[50 + i] = (c < 19) ? W2[j * 19 + c] : 0.0f;
    }
    if (t < 20) g_stage[250 + t] = (t < 19) ? b2[t] : 0.0f;
}

__global__ void __launch_bounds__(TPB, 4) edge_mlp_kernel(
    const float* __restrict__ src, const float* __restrict__ dst,
    const float* __restrict__ ea,  const float* __restrict__ u,
    const int* __restrict__ batch32,
    float* __restrict__ out, int E)
{
    __shared__ __align__(16) float wbuf[WARPS][EPW * 19];  // 2432 B per warp

    const float* cW1  = cpar;            // [4][10]
    const float* cb1  = cpar + 40;
    const float* cW2p = cpar + 50;       // [10][20]
    const float* cb2p = cpar + 250;      // [20]

    const int tid  = threadIdx.x;
    const int lane = tid & 31;
    const int w    = tid >> 5;
    const int is64 = g_batch_is64;                         // uniform

    const int we0 = blockIdx.x * EPB + w * EPW;            // warp's first edge
    const int e   = we0 + lane;
    const int ec  = (e < E) ? e : 0;

    // ---- coalesced streaming inputs + L1-resident u gather ----
    const float xs = __ldcs(src + ec);
    const float xd = __ldcs(dst + ec);
    const float xa = __ldcs(ea + ec);
    const int   bi = __ldcs(batch32 + ((size_t)ec << is64));
    const float xu = __ldg(u + bi);

    // broadcast-packed inputs for the packed hidden layer
    const u64 xsp = pack2(xs, xs);
    const u64 xdp = pack2(xd, xd);
    const u64 xap = pack2(xa, xa);
    const u64 xup = pack2(xu, xu);

    u64 op[10];                                            // packed output pairs

#pragma unroll
    for (int jp = 0; jp < 5; jp++) {
        // hidden pair (j = 2jp, 2jp+1): 4 FFMA2 + bias pair addend
        u64 hp = ffma2(xsp, cpair(&cW1[ 0 + 2*jp]),
                 ffma2(xdp, cpair(&cW1[10 + 2*jp]),
                 ffma2(xap, cpair(&cW1[20 + 2*jp]),
                 ffma2(xup, cpair(&cW1[30 + 2*jp]), cpair(&cb1[2*jp])))));
        float h0, h1; unpack2(hp, h0, h1);
        h0 = fmaxf(h0, 0.0f);
        h1 = fmaxf(h1, 0.0f);
        const u64 hb0 = pack2(h0, h0);
        const u64 hb1 = pack2(h1, h1);

        const int j0 = 2 * jp, j1 = 2 * jp + 1;
        if (jp == 0) {
#pragma unroll
            for (int k = 0; k < 10; k++)        // bias folded as addend
                op[k] = ffma2(hb0, cpair(&cW2p[j0 * 20 + 2*k]), cpair(&cb2p[2*k]));
        } else {
#pragma unroll
            for (int k = 0; k < 10; k++)
                op[k] = ffma2(hb0, cpair(&cW2p[j0 * 20 + 2*k]), op[k]);
        }
#pragma unroll
        for (int k = 0; k < 10; k++)
            op[k] = ffma2(hb1, cpair(&cW2p[j1 * 20 + 2*k]), op[k]);
    }

    // ---- stage to warp-private buffer (stride 19: conflict-free) ----
    if (e < E) {
#pragma unroll
        for (int k = 0; k < 9; k++) {
            float lo, hi; unpack2(op[k], lo, hi);
            wbuf[w][lane * 19 + 2*k    ] = lo;
            wbuf[w][lane * 19 + 2*k + 1] = hi;
        }
        float lo, hi; unpack2(op[9], lo, hi);
        wbuf[w][lane * 19 + 18] = lo;            // pad half (hi) discarded
    }
    __syncwarp();

    // ---- coalesced streaming copy-out (warp base 16B-aligned: 32*76 B) ----
    int nv = E - we0;
    if (nv > EPW) nv = EPW;
    if (nv < 0)   nv = 0;
    const int nf  = nv * 19;
    const int nf4 = nf >> 2;
    float4* gout = reinterpret_cast<float4*>(out + (size_t)we0 * 19);
    const float4* sf = reinterpret_cast<const float4*>(&wbuf[w][0]);
#pragma unroll 5
    for (int i = lane; i < nf4; i += 32) __stcs(gout + i, sf[i]);
    if (lane < (nf & 3))
        out[(size_t)we0 * 19 + nf4 * 4 + lane] = wbuf[w][nf4 * 4 + lane];
}

extern "C" void kernel_launch(void* const* d_in, const int* in_sizes, int n_in,
                              void* d_out, int out_size)
{
    const float* src   = (const float*)d_in[0];
    const float* dst   = (const float*)d_in[1];
    const float* ea    = (const float*)d_in[2];
    const float* u     = (const float*)d_in[3];
    const int*   batch = (const int*)d_in[4];
    const float* W1    = (const float*)d_in[5];
    const float* b1    = (const float*)d_in[6];
    const float* W2    = (const float*)d_in[7];
    const float* b2    = (const float*)d_in[8];

    const int E = in_sizes[0];

    // Node 1: detector + padded constant-image staging (one tiny kernel).
    prep_kernel<<<1, 256>>>(W1, b1, W2, b2, batch);

    // Node 2: single 1080-byte D2D copy into constant memory (graph-legal).
    void *dst_sym = nullptr, *src_sym = nullptr;
    cudaGetSymbolAddress(&dst_sym, cpar);
    cudaGetSymbolAddress(&src_sym, g_stage);
    cudaMemcpyAsync(dst_sym, src_sym, 270 * sizeof(float),
                    cudaMemcpyDeviceToDevice, 0);

    // Node 3: main kernel.
    const int grid = (E + EPB - 1) / EPB;
    edge_mlp_kernel<<<grid, TPB>>>(src, dst, ea, u, batch, (float*)d_out, E);
}

// round 16
// speedup vs baseline: 1.3329x; 1.3329x over previous
#include <cuda_runtime.h>

#define TPB   256
#define WARPS (TPB / 32)
#define EPW   32                 // edges per warp (ILP=1)
#define EPB   (WARPS * EPW)      // 256 edges per block

// Constant image as native float2 pairs (LDC.64 via direct member indexing,
// no reinterpret_cast of constant space anywhere).
//   W1p [4][5]   : W1 row k, cols (2jp,2jp+1) -> W1p[k][jp]
//   b1p [5]      : b1 pair jp
//   W2p [10][10] : W2 row j, cols (2k,2k+1), col 19 padded 0 -> W2p[j][k]
//   b2p [10]     : b2 pairs, slot 19 padded 0
struct __align__(16) Params {
    float2 W1p[4][5];
    float2 b1p[5];
    float2 W2p[10][10];
    float2 b2p[10];
};
__constant__ Params cP;
__device__  Params g_stage;      // built by prep_kernel, copied into cP

// 1 if `batch` is int64 (odd int32 words are zero high-halves), else 0.
__device__ int g_batch_is64;

typedef unsigned long long u64;

__device__ __forceinline__ u64 pack2(float lo, float hi) {
    u64 r; asm("mov.b64 %0, {%1, %2};" : "=l"(r) : "f"(lo), "f"(hi)); return r;
}
__device__ __forceinline__ u64 f2u(float2 v) {
    u64 r; asm("mov.b64 %0, {%1, %2};" : "=l"(r) : "f"(v.x), "f"(v.y)); return r;
}
__device__ __forceinline__ void unpack2(u64 v, float& lo, float& hi) {
    asm("mov.b64 {%0, %1}, %2;" : "=f"(lo), "=f"(hi) : "l"(v));
}
// Blackwell packed dual-fp32 FMA (2 FLOPs/instr; ptxas never auto-fuses this)
__device__ __forceinline__ u64 ffma2(u64 a, u64 b, u64 c) {
    u64 d; asm("fma.rn.f32x2 %0, %1, %2, %3;" : "=l"(d) : "l"(a), "l"(b), "l"(c));
    return d;
}

// One launch: batch-width detector + padded staging image.
__global__ void prep_kernel(const float* __restrict__ W1,
                            const float* __restrict__ b1,
                            const float* __restrict__ W2,
                            const float* __restrict__ b2,
                            const int* __restrict__ b32)
{
    const int t = threadIdx.x;
    if (t == 0) {
        int z = 0;
#pragma unroll
        for (int i = 1; i < 64; i += 2) z |= b32[i];
        g_batch_is64 = (z == 0) ? 1 : 0;
    }
    float* gs = reinterpret_cast<float*>(&g_stage);
    // floats [0..39]: W1 row-major
    if (t < 40) gs[t] = W1[t];
    // floats [40..49]: b1
    if (t < 10) gs[40 + t] = b1[t];
    // floats [50..249]: W2 padded to [10][20], col 19 = 0
    for (int i = t; i < 200; i += blockDim.x) {
        int j = i / 20, c = i % 20;
        gs[50 + i] = (c < 19) ? W2[j * 19 + c] : 0.0f;
    }
    // floats [250..269]: b2 padded, slot 19 = 0
    if (t < 20) gs[250 + t] = (t < 19) ? b2[t] : 0.0f;
}

__global__ void __launch_bounds__(TPB, 4) edge_mlp_kernel(
    const float* __restrict__ src, const float* __restrict__ dst,
    const float* __restrict__ ea,  const float* __restrict__ u,
    const int* __restrict__ batch32,
    float* __restrict__ out, int E)
{
    __shared__ __align__(16) float wbuf[WARPS][EPW * 19];  // 2432 B per warp

    const int tid  = threadIdx.x;
    const int lane = tid & 31;
    const int w    = tid >> 5;
    const int is64 = g_batch_is64;                         // uniform

    const int we0 = blockIdx.x * EPB + w * EPW;            // warp's first edge
    const int e   = we0 + lane;
    const int ec  = (e < E) ? e : 0;

    // ---- coalesced streaming inputs + L1-resident u gather ----
    const float xs = __ldcs(src + ec);
    const float xd = __ldcs(dst + ec);
    const float xa = __ldcs(ea + ec);
    const int   bi = __ldcs(batch32 + ((size_t)ec << is64));
    const float xu = __ldg(u + bi);

    // broadcast-packed inputs for the packed hidden layer
    const u64 xsp = pack2(xs, xs);
    const u64 xdp = pack2(xd, xd);
    const u64 xap = pack2(xa, xa);
    const u64 xup = pack2(xu, xu);

    u64 op[10];                                            // packed output pairs

#pragma unroll
    for (int jp = 0; jp < 5; jp++) {
        // hidden pair (j = 2jp, 2jp+1): 4 FFMA2, bias pair as addend
        u64 hp = ffma2(xsp, f2u(cP.W1p[0][jp]),
                 ffma2(xdp, f2u(cP.W1p[1][jp]),
                 ffma2(xap, f2u(cP.W1p[2][jp]),
                 ffma2(xup, f2u(cP.W1p[3][jp]), f2u(cP.b1p[jp])))));
        float h0, h1; unpack2(hp, h0, h1);
        h0 = fmaxf(h0, 0.0f);
        h1 = fmaxf(h1, 0.0f);
        const u64 hb0 = pack2(h0, h0);
        const u64 hb1 = pack2(h1, h1);

        const int j0 = 2 * jp, j1 = 2 * jp + 1;
        if (jp == 0) {
#pragma unroll
            for (int k = 0; k < 10; k++)        // bias folded as addend
                op[k] = ffma2(hb0, f2u(cP.W2p[j0][k]), f2u(cP.b2p[k]));
        } else {
#pragma unroll
            for (int k = 0; k < 10; k++)
                op[k] = ffma2(hb0, f2u(cP.W2p[j0][k]), op[k]);
        }
#pragma unroll
        for (int k = 0; k < 10; k++)
            op[k] = ffma2(hb1, f2u(cP.W2p[j1][k]), op[k]);
    }

    // ---- stage to warp-private buffer (stride 19: conflict-free) ----
    if (e < E) {
#pragma unroll
        for (int k = 0; k < 9; k++) {
            float lo, hi; unpack2(op[k], lo, hi);
            wbuf[w][lane * 19 + 2*k    ] = lo;
            wbuf[w][lane * 19 + 2*k + 1] = hi;
        }
        float lo, hi; unpack2(op[9], lo, hi);
        wbuf[w][lane * 19 + 18] = lo;            // pad half (hi) discarded
    }
    __syncwarp();

    // ---- coalesced streaming copy-out (warp base 16B-aligned: 32*76 B) ----
    int nv = E - we0;
    if (nv > EPW) nv = EPW;
    if (nv < 0)   nv = 0;
    const int nf  = nv * 19;
    const int nf4 = nf >> 2;
    float4* gout = reinterpret_cast<float4*>(out + (size_t)we0 * 19);
    const float4* sf = reinterpret_cast<const float4*>(&wbuf[w][0]);
#pragma unroll 5
    for (int i = lane; i < nf4; i += 32) __stcs(gout + i, sf[i]);
    if (lane < (nf & 3))
        out[(size_t)we0 * 19 + nf4 * 4 + lane] = wbuf[w][nf4 * 4 + lane];
}

extern "C" void kernel_launch(void* const* d_in, const int* in_sizes, int n_in,
                              void* d_out, int out_size)
{
    const float* src   = (const float*)d_in[0];
    const float* dst   = (const float*)d_in[1];
    const float* ea    = (const float*)d_in[2];
    const float* u     = (const float*)d_in[3];
    const int*   batch = (const int*)d_in[4];
    const float* W1    = (const float*)d_in[5];
    const float* b1    = (const float*)d_in[6];
    const float* W2    = (const float*)d_in[7];
    const float* b2    = (const float*)d_in[8];

    const int E = in_sizes[0];

    // Node 1: detector + padded staging image (one tiny kernel).
    prep_kernel<<<1, 256>>>(W1, b1, W2, b2, batch);

    // Node 2: single 1080-byte D2D copy into constant memory
    // (same API pattern that passed capture in Round 10).
    void *dst_sym = nullptr, *src_sym = nullptr;
    cudaGetSymbolAddress(&dst_sym, cP);
    cudaGetSymbolAddress(&src_sym, g_stage);
    cudaMemcpyAsync(dst_sym, src_sym, sizeof(Params),
                    cudaMemcpyDeviceToDevice, 0);

    // Node 3: main kernel.
    const int grid = (E + EPB - 1) / EPB;
    edge_mlp_kernel<<<grid, TPB>>>(src, dst, ea, u, batch, (float*)d_out, E);
}